// round 2
// baseline (speedup 1.0000x reference)
#include <cuda_runtime.h>
#include <cstdint>

// Shapes fixed by the problem: x [8192, 4096] f32, weight [4096, 4096] f32,
// scale [4096] f32, bias [4096] f32, out [8192, 4096] f32.
#define N_DIM   8192
#define IN_DIM  4096
#define OUT_DIM 4096
#define THRESH  0.1f

// Static device scratch (allocation-free per harness rules).
// Worst case: every weight nonzero -> OUT_DIM*IN_DIM entries.
// Entry encoding: e >= 0  -> +x[col=e] ; e < 0 -> -x[col=(-e-1)].
__device__ int   g_nnz[OUT_DIM];
__device__ short g_entries[(size_t)OUT_DIM * IN_DIM];

// ---------------------------------------------------------------------------
// Kernel A: ternarize weight rows and compact nonzero entries (CSR-ish).
// One warp per output row. Deterministic ordering via ballot prefix-sum:
// entries land in ascending column order every launch.
// ---------------------------------------------------------------------------
__global__ void __launch_bounds__(32)
ternarize_compress_kernel(const float* __restrict__ w) {
    const int o    = blockIdx.x;
    const int lane = threadIdx.x;

    const float* __restrict__ row = w + (size_t)o * IN_DIM;
    short* __restrict__ ent = g_entries + (size_t)o * IN_DIM;

    int count = 0;
    const unsigned lane_mask_lt = (1u << lane) - 1u;

    #pragma unroll 4
    for (int base = 0; base < IN_DIM; base += 32) {
        const int   col = base + lane;
        const float v   = row[col];
        // ternary: 0 if |v| < THRESH else sign(v)
        int t = 0;
        if (!(fabsf(v) < THRESH)) t = (v > 0.0f) ? 1 : -1;

        const unsigned mask = __ballot_sync(0xffffffffu, t != 0);
        if (t != 0) {
            const int pos = count + __popc(mask & lane_mask_lt);
            ent[pos] = (t > 0) ? (short)col : (short)(-col - 1);
        }
        count += __popc(mask);
    }
    if (lane == 0) g_nnz[o] = count;
}

// ---------------------------------------------------------------------------
// Kernel B: out[n, o] = (sum_{k in nnz(o)} sign_k * x[n, col_k] + bias[o]) * scale[o]
// One thread per FOUR consecutive output elements (float4 store, fully
// coalesced). nnz / bias / scale are tiny and hit L1/L2 across all n.
// For the bench dataset nnz(o) ~ 0, so this is a streaming 128 MB write.
// ---------------------------------------------------------------------------
__global__ void __launch_bounds__(256)
ternary_linear_kernel(const float* __restrict__ x,
                      const float* __restrict__ scale,
                      const float* __restrict__ bias,
                      float* __restrict__ out) {
    const int o4 = blockIdx.x * 256 + threadIdx.x;   // index of float4 group
    const int o  = o4 * 4;
    const int n  = blockIdx.y;
    if (o >= OUT_DIM) return;

    const float* __restrict__ xr = x + (size_t)n * IN_DIM;

    float acc[4];
    #pragma unroll
    for (int j = 0; j < 4; ++j) {
        const int oo  = o + j;
        const int nnz = g_nnz[oo];
        float a = 0.0f;
        if (nnz > 0) {
            const short* __restrict__ ent = g_entries + (size_t)oo * IN_DIM;
            for (int k = 0; k < nnz; ++k) {
                const int e = ent[k];
                if (e >= 0) a += xr[e];
                else        a -= xr[-e - 1];
            }
        }
        acc[j] = (a + bias[oo]) * scale[oo];
    }

    float4 v = make_float4(acc[0], acc[1], acc[2], acc[3]);
    *reinterpret_cast<float4*>(out + (size_t)n * OUT_DIM + o) = v;
}

// ---------------------------------------------------------------------------
// Launch
// ---------------------------------------------------------------------------
extern "C" void kernel_launch(void* const* d_in, const int* in_sizes, int n_in,
                              void* d_out, int out_size) {
    const float* x      = (const float*)d_in[0];
    const float* weight = (const float*)d_in[1];
    const float* scale  = (const float*)d_in[2];
    const float* bias   = (const float*)d_in[3];
    float*       out    = (float*)d_out;

    (void)in_sizes; (void)n_in; (void)out_size;

    // A: compress ternary weights (deterministic, coalesced).
    ternarize_compress_kernel<<<OUT_DIM, 32>>>(weight);

    // B: produce output (stream-ordered after A on the default stream).
    dim3 grid((OUT_DIM / 4 + 255) / 256, N_DIM);
    ternary_linear_kernel<<<grid, 256>>>(x, scale, bias, out);
}

// round 3
// speedup vs baseline: 1.5248x; 1.5248x over previous
#include <cuda_runtime.h>
#include <cstdint>

// Shapes fixed by the problem: x [8192, 4096] f32, weight [4096, 4096] f32,
// scale [4096] f32, bias [4096] f32, out [8192, 4096] f32.
#define N_DIM   8192
#define IN_DIM  4096
#define OUT_DIM 4096
#define THRESH  0.1f

// ---------------------------------------------------------------------------
// Static device scratch (allocation-free per harness rules).
// Entry encoding: e >= 0 -> +x[col=e] ; e < 0 -> -x[col=(-e-1)].
// ---------------------------------------------------------------------------
__device__ int   g_nnz[OUT_DIM];
__device__ float g_base[OUT_DIM];                       // bias[o] * scale[o]
__device__ short g_entries[(size_t)OUT_DIM * IN_DIM];
__device__ int   g_num_active;                          // #outputs with nnz>0
__device__ int   g_active[OUT_DIM];                     // their indices (set semantics)

// ---------------------------------------------------------------------------
// Kernel 0: reset the active-output counter (graph replays reuse state).
// ---------------------------------------------------------------------------
__global__ void init_kernel() { g_num_active = 0; }

// ---------------------------------------------------------------------------
// Kernel A: ternarize + compact. 8 warps/block, one warp per weight row.
// float4 loads (high MLP); shfl inclusive-scan compaction keeps entries in
// ascending column order (deterministic every launch).
// ---------------------------------------------------------------------------
__global__ void __launch_bounds__(256)
ternarize_compress_kernel(const float* __restrict__ w,
                          const float* __restrict__ scale,
                          const float* __restrict__ bias) {
    const int warp = threadIdx.x >> 5;
    const int lane = threadIdx.x & 31;
    const int o    = blockIdx.x * 8 + warp;            // row index

    const float4* __restrict__ row =
        reinterpret_cast<const float4*>(w + (size_t)o * IN_DIM);
    short* __restrict__ ent = g_entries + (size_t)o * IN_DIM;

    int count = 0;                                     // running row nnz

    // 1024 float4 per row / 32 lanes = 32 iterations
    #pragma unroll 4
    for (int it = 0; it < 32; ++it) {
        const int  v4i = it * 32 + lane;               // float4 index in row
        const float4 v = row[v4i];

        float vv[4] = {v.x, v.y, v.z, v.w};
        int   t[4];
        int   cnt = 0;
        #pragma unroll
        for (int j = 0; j < 4; ++j) {
            int tj = 0;
            if (!(fabsf(vv[j]) < THRESH)) tj = (vv[j] > 0.0f) ? 1 : -1;
            t[j] = tj;
            cnt += (tj != 0);
        }

        // warp inclusive scan of cnt
        int scan = cnt;
        #pragma unroll
        for (int d = 1; d < 32; d <<= 1) {
            int up = __shfl_up_sync(0xffffffffu, scan, d);
            if (lane >= d) scan += up;
        }
        int offs  = count + (scan - cnt);              // exclusive prefix
        int total = __shfl_sync(0xffffffffu, scan, 31);

        if (cnt > 0) {
            const int colbase = v4i * 4;
            #pragma unroll
            for (int j = 0; j < 4; ++j) {
                if (t[j] != 0) {
                    const int col = colbase + j;
                    ent[offs++] = (t[j] > 0) ? (short)col : (short)(-col - 1);
                }
            }
        }
        count += total;
    }

    if (lane == 0) {
        g_nnz[o]  = count;
        g_base[o] = bias[o] * scale[o];
        if (count > 0) {
            const int idx = atomicAdd(&g_num_active, 1);
            g_active[idx] = o;
        }
    }
}

// ---------------------------------------------------------------------------
// Kernel B: broadcast write. out[n, o] = g_base[o] for all n.
// Block = 256 threads covering 1024 consecutive o (one float4 each),
// loaded ONCE, then streamed to ROWS_PER_BLOCK rows. Pure STG after the
// first iteration -> HBM-write bound.
// ---------------------------------------------------------------------------
#define ROWS_PER_BLOCK 32
__global__ void __launch_bounds__(256)
broadcast_write_kernel(float* __restrict__ out) {
    const int o      = (blockIdx.x * 256 + threadIdx.x) * 4;   // o-tile
    const int n_base = blockIdx.y * ROWS_PER_BLOCK;

    const float4 v = *reinterpret_cast<const float4*>(g_base + o);

    float4* __restrict__ dst =
        reinterpret_cast<float4*>(out + (size_t)n_base * OUT_DIM + o);
    const size_t stride4 = OUT_DIM / 4;                        // float4 row stride

    #pragma unroll 8
    for (int r = 0; r < ROWS_PER_BLOCK; ++r)
        dst[(size_t)r * stride4] = v;
}

// ---------------------------------------------------------------------------
// Kernel C: fixup for active outputs (nnz>0). Fixed grid; loops over
// N_DIM * num_active (n, active) pairs. num_active ~ 0 on this dataset,
// so this exits in ~2us, but stays fully general for dense weights.
// ---------------------------------------------------------------------------
__global__ void __launch_bounds__(256)
fixup_kernel(const float* __restrict__ x,
             const float* __restrict__ scale,
             const float* __restrict__ bias,
             float* __restrict__ out) {
    const int na = g_num_active;
    if (na == 0) return;

    const long long total  = (long long)N_DIM * na;
    const long long gsz    = (long long)gridDim.x * 256;
    for (long long idx = blockIdx.x * 256LL + threadIdx.x; idx < total; idx += gsz) {
        const int ai = (int)(idx % na);
        const int n  = (int)(idx / na);
        const int o  = g_active[ai];

        const float* __restrict__ xr  = x + (size_t)n * IN_DIM;
        const short* __restrict__ ent = g_entries + (size_t)o * IN_DIM;
        const int nnz = g_nnz[o];

        float acc = 0.0f;
        for (int k = 0; k < nnz; ++k) {
            const int e = ent[k];
            if (e >= 0) acc += xr[e];
            else        acc -= xr[-e - 1];
        }
        out[(size_t)n * OUT_DIM + o] = (acc + bias[o]) * scale[o];
    }
}

// ---------------------------------------------------------------------------
// Launch
// ---------------------------------------------------------------------------
extern "C" void kernel_launch(void* const* d_in, const int* in_sizes, int n_in,
                              void* d_out, int out_size) {
    const float* x      = (const float*)d_in[0];
    const float* weight = (const float*)d_in[1];
    const float* scale  = (const float*)d_in[2];
    const float* bias   = (const float*)d_in[3];
    float*       out    = (float*)d_out;

    (void)in_sizes; (void)n_in; (void)out_size;

    init_kernel<<<1, 1>>>();

    // A: compress ternary weights + precompute base = bias*scale.
    ternarize_compress_kernel<<<OUT_DIM / 8, 256>>>(weight, scale, bias);

    // B: broadcast base to all 8192 rows (pure streaming write).
    dim3 gridB(OUT_DIM / 1024, N_DIM / ROWS_PER_BLOCK);
    broadcast_write_kernel<<<gridB, 256>>>(out);

    // C: exact fixup for the (rare) nonzero ternary outputs.
    fixup_kernel<<<512, 256>>>(x, scale, bias, out);
}